// round 15
// baseline (speedup 1.0000x reference)
#include <cuda_runtime.h>
#include <cuda_fp16.h>
#include <cstdint>

#define TOK   4096
#define EMB   512
#define QKVN  1536
#define HEADS 8
#define DH    64
#define SCALE 0.125f

#define HSTRIDE (TOK * DH)           // 262144

#define KTV_SPLITS 8

// ---------------- scratch (device globals) ----------------
__device__ float g_kf[HEADS * TOK * DH];             // K fp32 [h][n][d] (coarse)
__device__ float g_qsum_part[32 * HEADS * DH];       // [m_block][h*64+d]
__device__ float g_ktv_part[KTV_SPLITS * HEADS * DH * DH];  // M^T partials [d2][d1]
__device__ __half g_mT[HEADS * DH * DH];             // reduced M^T fp16 [h][d2][d1]
__device__ int   g_ctr[HEADS];                       // ktv completion counters

__device__ __half g_a_hi[TOK * EMB];                 // A = x^T  [4096, 512]
__device__ __half g_b_hi[QKVN * EMB];                // B = W^T  [1536, 512]
__device__ __half g_qh[HEADS * TOK * DH];            // Q fp16 [h][n][d]
__device__ __half g_kT[HEADS * DH * TOK];            // K^T fp16 [h][d][n]
__device__ __half g_vT[HEADS * DH * TOK];            // V^T fp16 [h][d][n]

// ---------------- helpers ----------------
__device__ __forceinline__ uint32_t smem_u32(const void* p) {
    uint32_t a;
    asm("{ .reg .u64 t; cvta.to.shared.u64 t, %1; cvt.u32.u64 %0, t; }" : "=r"(a) : "l"(p));
    return a;
}
__device__ __forceinline__ uint32_t lds32(uint32_t a) {
    uint32_t v;
    asm volatile("ld.shared.b32 %0, [%1];" : "=r"(v) : "r"(a));
    return v;
}
__device__ __forceinline__ void cp_async16(uint32_t saddr, const void* gaddr) {
    asm volatile("cp.async.cg.shared.global [%0], [%1], 16;" :: "r"(saddr), "l"(gaddr));
}
__device__ __forceinline__ void cp_commit() { asm volatile("cp.async.commit_group;"); }
__device__ __forceinline__ void cp_wait1()  { asm volatile("cp.async.wait_group 1;"); }
__device__ __forceinline__ void cp_wait0()  { asm volatile("cp.async.wait_group 0;"); }

__device__ __forceinline__ void mma_f16(float& c0, float& c1, float& c2, float& c3,
                                        uint32_t a0, uint32_t a1, uint32_t a2, uint32_t a3,
                                        uint32_t b0, uint32_t b1) {
    asm volatile(
        "mma.sync.aligned.m16n8k16.row.col.f32.f16.f16.f32 "
        "{%0,%1,%2,%3}, {%4,%5,%6,%7}, {%8,%9}, {%0,%1,%2,%3};"
        : "+f"(c0), "+f"(c1), "+f"(c2), "+f"(c3)
        : "r"(a0), "r"(a1), "r"(a2), "r"(a3), "r"(b0), "r"(b1));
}

// ---------------------------------------------------------------------------
// Merged pre-pass: transpose x->ahi and W->bhi, half2 stores
// ---------------------------------------------------------------------------
#define XBLKS (TOK / 32)      // 128
__global__ __launch_bounds__(256) void conv_transpose2(const float* __restrict__ x,
                                                       const float* __restrict__ W,
                                                       __half* __restrict__ ahi,
                                                       __half* __restrict__ bhi) {
    __shared__ float tile[32][33];
    int tid = threadIdx.x;
    int tx = tid & 31, ty = tid >> 5;
    int bx = blockIdx.x;
    const float* src;
    __half* dst;
    int Mcols, m0;
    if (bx < XBLKS) { src = x; dst = ahi; Mcols = TOK;  m0 = bx * 32; }
    else            { src = W; dst = bhi; Mcols = QKVN; m0 = (bx - XBLKS) * 32; }
    int k0 = blockIdx.y * 32;
#pragma unroll
    for (int j = 0; j < 4; j++)
        tile[ty + j * 8][tx] = src[(size_t)(k0 + ty + j * 8) * Mcols + m0 + tx];
    __syncthreads();
    int r2 = tid >> 4;
    int c2 = tid & 15;
#pragma unroll
    for (int j = 0; j < 2; j++) {
        int row = r2 + j * 16;
        int m = m0 + row;
        __half2 v = __floats2half2_rn(tile[c2 * 2][row], tile[c2 * 2 + 1][row]);
        *reinterpret_cast<__half2*>(&dst[(size_t)m * EMB + k0 + c2 * 2]) = v;
    }
}

// ---------------------------------------------------------------------------
// mma.sync QKV GEMM; epilogue: Q fp16, K fp32+fp16T, V fp16T
// Also resets g_ctr (runs strictly before ktv_mma).
// ---------------------------------------------------------------------------
#define GBM 128
#define GBN 128
#define GBK 32
#define ROWB   80
#define TILE_B (128 * ROWB)
#define T_AHI  0
#define T_BHI  (1 * TILE_B)
#define STG_B  (2 * TILE_B)
#define SM_BIAS (2 * STG_B)
#define SM_QS   (SM_BIAS + 512)
#define SM_TOT  (SM_QS + 1024)

__global__ void __launch_bounds__(256, 2) qkv_gemm_mma(const float* __restrict__ bias) {
    extern __shared__ char smem[];
    const uint32_t sb = smem_u32(smem);
    const int tid  = threadIdx.x;
    const int wid  = tid >> 5;
    const int lane = tid & 31;
    const int g    = lane >> 2;
    const int tg   = lane & 3;
    const int wm   = wid >> 2;
    const int wn   = wid & 3;
    const int o0   = blockIdx.x * GBN;
    const int m0   = blockIdx.y * GBM;

    if (blockIdx.x == 0 && blockIdx.y == 0 && tid < HEADS) g_ctr[tid] = 0;

    if (tid < 128) *reinterpret_cast<float*>(smem + SM_BIAS + tid * 4) = bias[o0 + tid];

    const __half* srcs[2] = {
        &g_a_hi[(size_t)m0 * EMB], &g_b_hi[(size_t)o0 * EMB]};

    auto issue = [&](int chunk) {
        const int kt = chunk * GBK;
        const uint32_t stage = sb + (chunk & 1) * STG_B;
#pragma unroll
        for (int t = 0; t < 2; t++) {
            const __half* gp = srcs[t] + kt;
            const uint32_t tb = stage + t * TILE_B;
#pragma unroll
            for (int i = 0; i < 2; i++) {
                int lin = tid + i * 256;
                int row = lin >> 2;
                int seg = lin & 3;
                cp_async16(tb + row * ROWB + seg * 16, gp + (size_t)row * EMB + seg * 8);
            }
        }
        cp_commit();
    };

    float acc[4][4][4];
#pragma unroll
    for (int i = 0; i < 4; i++)
#pragma unroll
        for (int j = 0; j < 4; j++)
#pragma unroll
            for (int c = 0; c < 4; c++) acc[i][j][c] = 0.f;

    issue(0);

    const uint32_t aRow0 = wm * 64 + g;
    const uint32_t bRow0 = wn * 32 + g;

    for (int chunk = 0; chunk < EMB / GBK; ++chunk) {
        if (chunk + 1 < EMB / GBK) { issue(chunk + 1); cp_wait1(); }
        else                       { cp_wait0(); }
        __syncthreads();

        const uint32_t stage = sb + (chunk & 1) * STG_B;

#pragma unroll
        for (int kk = 0; kk < 2; kk++) {
            const uint32_t klo = kk * 32 + tg * 4;

            uint32_t afr[4][4], bfr[4][2];
#pragma unroll
            for (int nt = 0; nt < 4; nt++) {
                uint32_t base = stage + (bRow0 + nt * 8) * ROWB + klo + T_BHI;
                bfr[nt][0] = lds32(base);
                bfr[nt][1] = lds32(base + 16);
            }
#pragma unroll
            for (int mt = 0; mt < 4; mt++) {
                uint32_t base = stage + (aRow0 + mt * 16) * ROWB + klo + T_AHI;
                afr[mt][0] = lds32(base);
                afr[mt][1] = lds32(base + 8 * ROWB);
                afr[mt][2] = lds32(base + 16);
                afr[mt][3] = lds32(base + 8 * ROWB + 16);
            }
#pragma unroll
            for (int mt = 0; mt < 4; mt++)
#pragma unroll
                for (int nt = 0; nt < 4; nt++)
                    mma_f16(acc[mt][nt][0], acc[mt][nt][1], acc[mt][nt][2], acc[mt][nt][3],
                            afr[mt][0], afr[mt][1], afr[mt][2], afr[mt][3],
                            bfr[nt][0], bfr[nt][1]);
        }
        __syncthreads();
    }

    const float* sbias = reinterpret_cast<const float*>(smem + SM_BIAS);
#pragma unroll
    for (int mt = 0; mt < 4; mt++) {
        const int m = m0 + wm * 64 + mt * 16 + g;
#pragma unroll
        for (int nt = 0; nt < 4; nt++) {
            const int off = wn * 32 + nt * 8 + 2 * tg;
            const int o = o0 + off;
            const int part = o >> 9;
            const int h = (o >> 6) & 7;
            const int d = o & 63;
            const float bv0 = sbias[off], bv1 = sbias[off + 1];
            const float v00 = acc[mt][nt][0] + bv0;
            const float v01 = acc[mt][nt][1] + bv1;
            const float v10 = acc[mt][nt][2] + bv0;
            const float v11 = acc[mt][nt][3] + bv1;
            if (part == 0) {
                __half* dq = &g_qh[(size_t)h * HSTRIDE];
                *reinterpret_cast<__half2*>(&dq[(size_t)m * DH + d]) = __floats2half2_rn(v00, v01);
                *reinterpret_cast<__half2*>(&dq[(size_t)(m + 8) * DH + d]) = __floats2half2_rn(v10, v11);
            } else if (part == 1) {
                float* base = &g_kf[(size_t)h * HSTRIDE];
                *reinterpret_cast<float2*>(&base[(size_t)m * DH + d]) = make_float2(v00, v01);
                *reinterpret_cast<float2*>(&base[(size_t)(m + 8) * DH + d]) = make_float2(v10, v11);
                __half* dT = &g_kT[(size_t)h * DH * TOK];
                dT[(size_t)(d + 0) * TOK + m]     = __float2half_rn(v00);
                dT[(size_t)(d + 1) * TOK + m]     = __float2half_rn(v01);
                dT[(size_t)(d + 0) * TOK + m + 8] = __float2half_rn(v10);
                dT[(size_t)(d + 1) * TOK + m + 8] = __float2half_rn(v11);
            } else {
                __half* dT = &g_vT[(size_t)h * DH * TOK];
                dT[(size_t)(d + 0) * TOK + m]     = __float2half_rn(v00);
                dT[(size_t)(d + 1) * TOK + m]     = __float2half_rn(v01);
                dT[(size_t)(d + 0) * TOK + m + 8] = __float2half_rn(v10);
                dT[(size_t)(d + 1) * TOK + m + 8] = __float2half_rn(v11);
            }
        }
    }

    // fused qsum partial
    if (o0 < 512) {
        float* qs = reinterpret_cast<float*>(smem + SM_QS);
        float cs[8];
#pragma unroll
        for (int nt = 0; nt < 4; nt++)
#pragma unroll
            for (int j = 0; j < 2; j++) {
                const int off = wn * 32 + nt * 8 + 2 * tg + j;
                float s = 8.f * sbias[off];
#pragma unroll
                for (int mt = 0; mt < 4; mt++)
                    s += acc[mt][nt][j] + acc[mt][nt][j + 2];
                cs[nt * 2 + j] = s;
            }
#pragma unroll
        for (int i = 0; i < 8; i++) {
#pragma unroll
            for (int off = 4; off < 32; off <<= 1)
                cs[i] += __shfl_xor_sync(0xffffffffu, cs[i], off);
        }
        if (g == 0) {
#pragma unroll
            for (int nt = 0; nt < 4; nt++)
#pragma unroll
                for (int j = 0; j < 2; j++)
                    qs[wm * 128 + wn * 32 + nt * 8 + 2 * tg + j] = cs[nt * 2 + j];
        }
        __syncthreads();
        if (tid < 128)
            g_qsum_part[blockIdx.y * 512 + o0 + tid] = qs[tid] + qs[128 + tid];
    }
}

// ---------------------------------------------------------------------------
// KtV via mma.sync (A=V^T, B=K^T -> partials hold M^T[d2][d1]).
// Last finisher per head reduces 8 partials (fixed order) -> g_mT fp16.
// ---------------------------------------------------------------------------
#define KT_ROWB 528
#define KT_TILE (64 * KT_ROWB)
#define KTV_SMEM (2 * KT_TILE)

__global__ void __launch_bounds__(128) ktv_mma() {
    extern __shared__ char ksm[];
    const uint32_t sb = smem_u32(ksm);
    const int h = blockIdx.x;
    const int split = blockIdx.y;          // 0..7
    const int tid = threadIdx.x;
    const int lane = tid & 31;
    const int w = tid >> 5;
    const int grow = lane >> 2;
    const int tg = lane & 3;

    float acc[8][4];
#pragma unroll
    for (int nt = 0; nt < 8; nt++)
#pragma unroll
        for (int c = 0; c < 4; c++) acc[nt][c] = 0.f;

    const uint32_t aBase = sb + (w * 16 + grow) * KT_ROWB + tg * 4;
    const uint32_t bBase = sb + KT_TILE + grow * KT_ROWB + tg * 4;

    for (int cc = 0; cc < 2; cc++) {
        const __half* Asrc = &g_vT[(size_t)h * DH * TOK + split * 512 + cc * 256];
        const __half* Bsrc = &g_kT[(size_t)h * DH * TOK + split * 512 + cc * 256];
#pragma unroll
        for (int i = 0; i < 16; i++) {
            int lin = tid + i * 128;
            int r = lin >> 5;
            int c = lin & 31;
            cp_async16(sb + r * KT_ROWB + c * 16, Asrc + (size_t)r * TOK + c * 8);
            cp_async16(sb + KT_TILE + r * KT_ROWB + c * 16, Bsrc + (size_t)r * TOK + c * 8);
        }
        cp_commit();
        cp_wait0();
        __syncthreads();

#pragma unroll
        for (int kk = 0; kk < 16; kk++) {
            const uint32_t ko = kk * 32;
            uint32_t a0 = lds32(aBase + ko);
            uint32_t a1 = lds32(aBase + 8 * KT_ROWB + ko);
            uint32_t a2 = lds32(aBase + ko + 16);
            uint32_t a3 = lds32(aBase + 8 * KT_ROWB + ko + 16);
#pragma unroll
            for (int nt = 0; nt < 8; nt++) {
                uint32_t bb = bBase + nt * 8 * KT_ROWB + ko;
                uint32_t b0 = lds32(bb);
                uint32_t b1 = lds32(bb + 16);
                mma_f16(acc[nt][0], acc[nt][1], acc[nt][2], acc[nt][3],
                        a0, a1, a2, a3, b0, b1);
            }
        }
        __syncthreads();
    }

    float* dst = &g_ktv_part[(size_t)split * (HEADS * DH * DH) + (size_t)h * DH * DH];
    const int d2 = w * 16 + grow;
#pragma unroll
    for (int nt = 0; nt < 8; nt++) {
        const int d1 = nt * 8 + 2 * tg;
        *reinterpret_cast<float2*>(&dst[d2 * DH + d1]) = make_float2(acc[nt][0], acc[nt][1]);
        *reinterpret_cast<float2*>(&dst[(d2 + 8) * DH + d1]) = make_float2(acc[nt][2], acc[nt][3]);
    }

    // last-block-per-head reduction (threadFenceReduction idiom)
    __shared__ int is_last;
    __threadfence();
    if (tid == 0) is_last = (atomicAdd(&g_ctr[h], 1) == KTV_SPLITS - 1) ? 1 : 0;
    __syncthreads();
    if (is_last) {
        const float* p0 = &g_ktv_part[(size_t)h * DH * DH];
#pragma unroll
        for (int i = 0; i < 16; i++) {
            int lin = tid + i * 128;        // 0..2047 float2 pairs
            int rd2 = lin >> 5;
            int d1p = (lin & 31) * 2;
            float2 s = *reinterpret_cast<const float2*>(p0 + rd2 * DH + d1p);
#pragma unroll
            for (int sp = 1; sp < KTV_SPLITS; sp++) {
                float2 v = *reinterpret_cast<const float2*>(
                    p0 + (size_t)sp * (HEADS * DH * DH) + rd2 * DH + d1p);
                s.x += v.x; s.y += v.y;
            }
            *reinterpret_cast<__half2*>(&g_mT[(size_t)h * DH * DH + rd2 * DH + d1p]) =
                __floats2half2_rn(s.x, s.y);
        }
    }
}

// ---------------------------------------------------------------------------
// out via mma.sync: D[128, 64] = Qtile[128, 64] @ M[64, 64]
// A = Q fp16; B = M^T fp16 loaded directly (pre-reduced in ktv_mma).
// coarse fused (K fp32 path, exact).
// ---------------------------------------------------------------------------
#define OQ_ROWB 144
#define OSM_Q   0                           // 128*144 = 18432
#define OSM_MT  18432                       // 64*144  = 9216
#define OSM_QS  (OSM_MT + 9216)             // 27648
#define OSM_TOT (OSM_QS + 256)              // 27904

__global__ void __launch_bounds__(128) out_mma(float* __restrict__ coarse,
                                               float* __restrict__ out) {
    extern __shared__ char osm[];
    const uint32_t sb = smem_u32(osm);
    float* sQs = reinterpret_cast<float*>(osm + OSM_QS);

    const int h = blockIdx.x;
    const int nt = blockIdx.y;              // 0..31
    const int tid = threadIdx.x;
    const int lane = tid & 31;
    const int w = tid >> 5;
    const int grow = lane >> 2;
    const int tg = lane & 3;

    // stage Q tile fp16 + M^T fp16 via cp.async
    const __half* Qg = &g_qh[(size_t)h * HSTRIDE + (size_t)nt * 128 * DH];
#pragma unroll
    for (int i = 0; i < 8; i++) {
        int lin = tid + i * 128;
        int r = lin >> 3;
        int c = lin & 7;
        cp_async16(sb + OSM_Q + r * OQ_ROWB + c * 16, Qg + (size_t)r * DH + c * 8);
    }
    const __half* Mg = &g_mT[(size_t)h * DH * DH];
#pragma unroll
    for (int i = 0; i < 4; i++) {
        int lin = tid + i * 128;            // 0..511 16B chunks
        int r = lin >> 3;
        int c = lin & 7;
        cp_async16(sb + OSM_MT + r * OQ_ROWB + c * 16, Mg + (size_t)r * DH + c * 8);
    }
    cp_commit();

    // qsum reduce (32 partials, fixed order)
    if (tid < 64) {
        float q = 0.f;
#pragma unroll
        for (int sp = 0; sp < 32; sp++) q += g_qsum_part[sp * (HEADS * DH) + h * 64 + tid];
        sQs[tid] = q;
    }
    cp_wait0();
    __syncthreads();

    // coarse: 1 row/thread via K fp32 (exact path)
    {
        const int n = nt * 128 + tid;
        const float* Kr = &g_kf[(size_t)h * HSTRIDE + (size_t)n * DH];
        float cacc = 0.f;
#pragma unroll
        for (int d4 = 0; d4 < 64; d4 += 4) {
            float4 k4 = *reinterpret_cast<const float4*>(&Kr[d4]);
            cacc += k4.x * sQs[d4] + k4.y * sQs[d4 + 1] + k4.z * sQs[d4 + 2] + k4.w * sQs[d4 + 3];
        }
        coarse[h * TOK + n] = cacc * SCALE;
    }

    // mma: warp w owns rows w*32..w*32+31 (2 m-tiles), all 64 cols (8 n-tiles)
    float acc[2][8][4];
#pragma unroll
    for (int mt = 0; mt < 2; mt++)
#pragma unroll
        for (int ct = 0; ct < 8; ct++)
#pragma unroll
            for (int c = 0; c < 4; c++) acc[mt][ct][c] = 0.f;

    const uint32_t aBase = sb + OSM_Q + (w * 32 + grow) * OQ_ROWB + tg * 4;
    const uint32_t bBase = sb + OSM_MT + grow * OQ_ROWB + tg * 4;

#pragma unroll
    for (int kk = 0; kk < 4; kk++) {
        const uint32_t ko = kk * 32;
        uint32_t a[2][4];
#pragma unroll
        for (int mt = 0; mt < 2; mt++) {
            uint32_t ab = aBase + mt * 16 * OQ_ROWB + ko;
            a[mt][0] = lds32(ab);
            a[mt][1] = lds32(ab + 8 * OQ_ROWB);
            a[mt][2] = lds32(ab + 16);
            a[mt][3] = lds32(ab + 8 * OQ_ROWB + 16);
        }
#pragma unroll
        for (int ct = 0; ct < 8; ct++) {
            uint32_t bb = bBase + ct * 8 * OQ_ROWB + ko;
            uint32_t b0 = lds32(bb);
            uint32_t b1 = lds32(bb + 16);
#pragma unroll
            for (int mt = 0; mt < 2; mt++)
                mma_f16(acc[mt][ct][0], acc[mt][ct][1], acc[mt][ct][2], acc[mt][ct][3],
                        a[mt][0], a[mt][1], a[mt][2], a[mt][3], b0, b1);
        }
    }

#pragma unroll
    for (int mt = 0; mt < 2; mt++) {
        const int n = nt * 128 + w * 32 + mt * 16 + grow;
        float* op = &out[((size_t)h * TOK + n) * DH];
#pragma unroll
        for (int ct = 0; ct < 8; ct++) {
            const int d = ct * 8 + 2 * tg;
            *reinterpret_cast<float2*>(&op[d]) =
                make_float2(acc[mt][ct][0] * SCALE, acc[mt][ct][1] * SCALE);
            *reinterpret_cast<float2*>(&op[8 * DH + d]) =
                make_float2(acc[mt][ct][2] * SCALE, acc[mt][ct][3] * SCALE);
        }
    }
}

// ---------------------------------------------------------------------------
extern "C" void kernel_launch(void* const* d_in, const int* in_sizes, int n_in,
                              void* d_out, int out_size) {
    const float* x = (const float*)d_in[0];   // [512, 4096]
    const float* W = (const float*)d_in[1];   // [512, 1536]
    const float* b = (const float*)d_in[2];   // [1536]

    float* coarse = (float*)d_out;
    float* out    = (float*)d_out + HEADS * TOK;

    __half *ahi, *bhi;
    cudaGetSymbolAddress((void**)&ahi, g_a_hi);
    cudaGetSymbolAddress((void**)&bhi, g_b_hi);

    cudaFuncSetAttribute(qkv_gemm_mma, cudaFuncAttributeMaxDynamicSharedMemorySize, SM_TOT);
    cudaFuncSetAttribute(ktv_mma, cudaFuncAttributeMaxDynamicSharedMemorySize, KTV_SMEM);
    cudaFuncSetAttribute(out_mma, cudaFuncAttributeMaxDynamicSharedMemorySize, OSM_TOT);

    conv_transpose2<<<dim3(XBLKS + QKVN / 32, EMB / 32), 256>>>(x, W, ahi, bhi);

    qkv_gemm_mma<<<dim3(QKVN / GBN, TOK / GBM), 256, SM_TOT>>>(b);

    ktv_mma<<<dim3(HEADS, KTV_SPLITS), 128, KTV_SMEM>>>();
    out_mma<<<dim3(HEADS, 32), 128, OSM_TOT>>>(coarse, out);
}

// round 16
// speedup vs baseline: 1.1520x; 1.1520x over previous
#include <cuda_runtime.h>
#include <cuda_fp16.h>
#include <cstdint>

#define TOK   4096
#define EMB   512
#define QKVN  1536
#define HEADS 8
#define DH    64
#define SCALE 0.125f

#define HSTRIDE (TOK * DH)           // 262144

#define KTV_SPLITS 8

// ---------------- scratch (device globals) ----------------
__device__ float g_kf[HEADS * TOK * DH];             // K fp32 [h][n][d] (coarse)
__device__ float g_qsum_part[32 * HEADS * DH];       // [m_block][h*64+d]
__device__ float g_ktv_part[KTV_SPLITS * HEADS * DH * DH];  // M^T partials [d2][d1]

__device__ __half g_a_hi[TOK * EMB];                 // A = x^T  [4096, 512]
__device__ __half g_b_hi[QKVN * EMB];                // B = W^T  [1536, 512]
__device__ __half g_qh[HEADS * TOK * DH];            // Q fp16 [h][n][d]
__device__ __half g_kT[HEADS * DH * TOK];            // K^T fp16 [h][d][n]
__device__ __half g_vT[HEADS * DH * TOK];            // V^T fp16 [h][d][n]

// ---------------- helpers ----------------
__device__ __forceinline__ uint32_t smem_u32(const void* p) {
    uint32_t a;
    asm("{ .reg .u64 t; cvta.to.shared.u64 t, %1; cvt.u32.u64 %0, t; }" : "=r"(a) : "l"(p));
    return a;
}
__device__ __forceinline__ uint32_t lds32(uint32_t a) {
    uint32_t v;
    asm volatile("ld.shared.b32 %0, [%1];" : "=r"(v) : "r"(a));
    return v;
}
__device__ __forceinline__ void cp_async16(uint32_t saddr, const void* gaddr) {
    asm volatile("cp.async.cg.shared.global [%0], [%1], 16;" :: "r"(saddr), "l"(gaddr));
}
__device__ __forceinline__ void cp_commit() { asm volatile("cp.async.commit_group;"); }
__device__ __forceinline__ void cp_wait1()  { asm volatile("cp.async.wait_group 1;"); }
__device__ __forceinline__ void cp_wait0()  { asm volatile("cp.async.wait_group 0;"); }

__device__ __forceinline__ void mma_f16(float& c0, float& c1, float& c2, float& c3,
                                        uint32_t a0, uint32_t a1, uint32_t a2, uint32_t a3,
                                        uint32_t b0, uint32_t b1) {
    asm volatile(
        "mma.sync.aligned.m16n8k16.row.col.f32.f16.f16.f32 "
        "{%0,%1,%2,%3}, {%4,%5,%6,%7}, {%8,%9}, {%0,%1,%2,%3};"
        : "+f"(c0), "+f"(c1), "+f"(c2), "+f"(c3)
        : "r"(a0), "r"(a1), "r"(a2), "r"(a3), "r"(b0), "r"(b1));
}

// ---------------------------------------------------------------------------
// Merged pre-pass: transpose x->ahi and W->bhi, half2 stores
// ---------------------------------------------------------------------------
#define XBLKS (TOK / 32)      // 128
__global__ __launch_bounds__(256) void conv_transpose2(const float* __restrict__ x,
                                                       const float* __restrict__ W,
                                                       __half* __restrict__ ahi,
                                                       __half* __restrict__ bhi) {
    __shared__ float tile[32][33];
    int tid = threadIdx.x;
    int tx = tid & 31, ty = tid >> 5;
    int bx = blockIdx.x;
    const float* src;
    __half* dst;
    int Mcols, m0;
    if (bx < XBLKS) { src = x; dst = ahi; Mcols = TOK;  m0 = bx * 32; }
    else            { src = W; dst = bhi; Mcols = QKVN; m0 = (bx - XBLKS) * 32; }
    int k0 = blockIdx.y * 32;
#pragma unroll
    for (int j = 0; j < 4; j++)
        tile[ty + j * 8][tx] = src[(size_t)(k0 + ty + j * 8) * Mcols + m0 + tx];
    __syncthreads();
    int r2 = tid >> 4;
    int c2 = tid & 15;
#pragma unroll
    for (int j = 0; j < 2; j++) {
        int row = r2 + j * 16;
        int m = m0 + row;
        __half2 v = __floats2half2_rn(tile[c2 * 2][row], tile[c2 * 2 + 1][row]);
        *reinterpret_cast<__half2*>(&dst[(size_t)m * EMB + k0 + c2 * 2]) = v;
    }
}

// ---------------------------------------------------------------------------
// mma.sync QKV GEMM; epilogue: Q fp16, K fp32+fp16T, V fp16T
// ---------------------------------------------------------------------------
#define GBM 128
#define GBN 128
#define GBK 32
#define ROWB   80
#define TILE_B (128 * ROWB)
#define T_AHI  0
#define T_BHI  (1 * TILE_B)
#define STG_B  (2 * TILE_B)
#define SM_BIAS (2 * STG_B)
#define SM_QS   (SM_BIAS + 512)
#define SM_TOT  (SM_QS + 1024)

__global__ void __launch_bounds__(256, 2) qkv_gemm_mma(const float* __restrict__ bias) {
    extern __shared__ char smem[];
    const uint32_t sb = smem_u32(smem);
    const int tid  = threadIdx.x;
    const int wid  = tid >> 5;
    const int lane = tid & 31;
    const int g    = lane >> 2;
    const int tg   = lane & 3;
    const int wm   = wid >> 2;
    const int wn   = wid & 3;
    const int o0   = blockIdx.x * GBN;
    const int m0   = blockIdx.y * GBM;

    if (tid < 128) *reinterpret_cast<float*>(smem + SM_BIAS + tid * 4) = bias[o0 + tid];

    const __half* srcs[2] = {
        &g_a_hi[(size_t)m0 * EMB], &g_b_hi[(size_t)o0 * EMB]};

    auto issue = [&](int chunk) {
        const int kt = chunk * GBK;
        const uint32_t stage = sb + (chunk & 1) * STG_B;
#pragma unroll
        for (int t = 0; t < 2; t++) {
            const __half* gp = srcs[t] + kt;
            const uint32_t tb = stage + t * TILE_B;
#pragma unroll
            for (int i = 0; i < 2; i++) {
                int lin = tid + i * 256;
                int row = lin >> 2;
                int seg = lin & 3;
                cp_async16(tb + row * ROWB + seg * 16, gp + (size_t)row * EMB + seg * 8);
            }
        }
        cp_commit();
    };

    float acc[4][4][4];
#pragma unroll
    for (int i = 0; i < 4; i++)
#pragma unroll
        for (int j = 0; j < 4; j++)
#pragma unroll
            for (int c = 0; c < 4; c++) acc[i][j][c] = 0.f;

    issue(0);

    const uint32_t aRow0 = wm * 64 + g;
    const uint32_t bRow0 = wn * 32 + g;

    for (int chunk = 0; chunk < EMB / GBK; ++chunk) {
        if (chunk + 1 < EMB / GBK) { issue(chunk + 1); cp_wait1(); }
        else                       { cp_wait0(); }
        __syncthreads();

        const uint32_t stage = sb + (chunk & 1) * STG_B;

#pragma unroll
        for (int kk = 0; kk < 2; kk++) {
            const uint32_t klo = kk * 32 + tg * 4;

            uint32_t afr[4][4], bfr[4][2];
#pragma unroll
            for (int nt = 0; nt < 4; nt++) {
                uint32_t base = stage + (bRow0 + nt * 8) * ROWB + klo + T_BHI;
                bfr[nt][0] = lds32(base);
                bfr[nt][1] = lds32(base + 16);
            }
#pragma unroll
            for (int mt = 0; mt < 4; mt++) {
                uint32_t base = stage + (aRow0 + mt * 16) * ROWB + klo + T_AHI;
                afr[mt][0] = lds32(base);
                afr[mt][1] = lds32(base + 8 * ROWB);
                afr[mt][2] = lds32(base + 16);
                afr[mt][3] = lds32(base + 8 * ROWB + 16);
            }
#pragma unroll
            for (int mt = 0; mt < 4; mt++)
#pragma unroll
                for (int nt = 0; nt < 4; nt++)
                    mma_f16(acc[mt][nt][0], acc[mt][nt][1], acc[mt][nt][2], acc[mt][nt][3],
                            afr[mt][0], afr[mt][1], afr[mt][2], afr[mt][3],
                            bfr[nt][0], bfr[nt][1]);
        }
        __syncthreads();
    }

    const float* sbias = reinterpret_cast<const float*>(smem + SM_BIAS);
#pragma unroll
    for (int mt = 0; mt < 4; mt++) {
        const int m = m0 + wm * 64 + mt * 16 + g;
#pragma unroll
        for (int nt = 0; nt < 4; nt++) {
            const int off = wn * 32 + nt * 8 + 2 * tg;
            const int o = o0 + off;
            const int part = o >> 9;
            const int h = (o >> 6) & 7;
            const int d = o & 63;
            const float bv0 = sbias[off], bv1 = sbias[off + 1];
            const float v00 = acc[mt][nt][0] + bv0;
            const float v01 = acc[mt][nt][1] + bv1;
            const float v10 = acc[mt][nt][2] + bv0;
            const float v11 = acc[mt][nt][3] + bv1;
            if (part == 0) {
                __half* dq = &g_qh[(size_t)h * HSTRIDE];
                *reinterpret_cast<__half2*>(&dq[(size_t)m * DH + d]) = __floats2half2_rn(v00, v01);
                *reinterpret_cast<__half2*>(&dq[(size_t)(m + 8) * DH + d]) = __floats2half2_rn(v10, v11);
            } else if (part == 1) {
                float* base = &g_kf[(size_t)h * HSTRIDE];
                *reinterpret_cast<float2*>(&base[(size_t)m * DH + d]) = make_float2(v00, v01);
                *reinterpret_cast<float2*>(&base[(size_t)(m + 8) * DH + d]) = make_float2(v10, v11);
                __half* dT = &g_kT[(size_t)h * DH * TOK];
                dT[(size_t)(d + 0) * TOK + m]     = __float2half_rn(v00);
                dT[(size_t)(d + 1) * TOK + m]     = __float2half_rn(v01);
                dT[(size_t)(d + 0) * TOK + m + 8] = __float2half_rn(v10);
                dT[(size_t)(d + 1) * TOK + m + 8] = __float2half_rn(v11);
            } else {
                __half* dT = &g_vT[(size_t)h * DH * TOK];
                dT[(size_t)(d + 0) * TOK + m]     = __float2half_rn(v00);
                dT[(size_t)(d + 1) * TOK + m]     = __float2half_rn(v01);
                dT[(size_t)(d + 0) * TOK + m + 8] = __float2half_rn(v10);
                dT[(size_t)(d + 1) * TOK + m + 8] = __float2half_rn(v11);
            }
        }
    }

    // fused qsum partial
    if (o0 < 512) {
        float* qs = reinterpret_cast<float*>(smem + SM_QS);
        float cs[8];
#pragma unroll
        for (int nt = 0; nt < 4; nt++)
#pragma unroll
            for (int j = 0; j < 2; j++) {
                const int off = wn * 32 + nt * 8 + 2 * tg + j;
                float s = 8.f * sbias[off];
#pragma unroll
                for (int mt = 0; mt < 4; mt++)
                    s += acc[mt][nt][j] + acc[mt][nt][j + 2];
                cs[nt * 2 + j] = s;
            }
#pragma unroll
        for (int i = 0; i < 8; i++) {
#pragma unroll
            for (int off = 4; off < 32; off <<= 1)
                cs[i] += __shfl_xor_sync(0xffffffffu, cs[i], off);
        }
        if (g == 0) {
#pragma unroll
            for (int nt = 0; nt < 4; nt++)
#pragma unroll
                for (int j = 0; j < 2; j++)
                    qs[wm * 128 + wn * 32 + nt * 8 + 2 * tg + j] = cs[nt * 2 + j];
        }
        __syncthreads();
        if (tid < 128)
            g_qsum_part[blockIdx.y * 512 + o0 + tid] = qs[tid] + qs[128 + tid];
    }
}

// ---------------------------------------------------------------------------
// KtV via mma.sync (A=V^T, B=K^T -> partials hold M^T[d2][d1]) — r14 version
// ---------------------------------------------------------------------------
#define KT_ROWB 528
#define KT_TILE (64 * KT_ROWB)
#define KTV_SMEM (2 * KT_TILE)

__global__ void __launch_bounds__(128) ktv_mma() {
    extern __shared__ char ksm[];
    const uint32_t sb = smem_u32(ksm);
    const int h = blockIdx.x;
    const int split = blockIdx.y;          // 0..7
    const int tid = threadIdx.x;
    const int lane = tid & 31;
    const int w = tid >> 5;
    const int grow = lane >> 2;
    const int tg = lane & 3;

    float acc[8][4];
#pragma unroll
    for (int nt = 0; nt < 8; nt++)
#pragma unroll
        for (int c = 0; c < 4; c++) acc[nt][c] = 0.f;

    const uint32_t aBase = sb + (w * 16 + grow) * KT_ROWB + tg * 4;
    const uint32_t bBase = sb + KT_TILE + grow * KT_ROWB + tg * 4;

    for (int cc = 0; cc < 2; cc++) {
        const __half* Asrc = &g_vT[(size_t)h * DH * TOK + split * 512 + cc * 256];
        const __half* Bsrc = &g_kT[(size_t)h * DH * TOK + split * 512 + cc * 256];
#pragma unroll
        for (int i = 0; i < 16; i++) {
            int lin = tid + i * 128;
            int r = lin >> 5;
            int c = lin & 31;
            cp_async16(sb + r * KT_ROWB + c * 16, Asrc + (size_t)r * TOK + c * 8);
            cp_async16(sb + KT_TILE + r * KT_ROWB + c * 16, Bsrc + (size_t)r * TOK + c * 8);
        }
        cp_commit();
        cp_wait0();
        __syncthreads();

#pragma unroll
        for (int kk = 0; kk < 16; kk++) {
            const uint32_t ko = kk * 32;
            uint32_t a0 = lds32(aBase + ko);
            uint32_t a1 = lds32(aBase + 8 * KT_ROWB + ko);
            uint32_t a2 = lds32(aBase + ko + 16);
            uint32_t a3 = lds32(aBase + 8 * KT_ROWB + ko + 16);
#pragma unroll
            for (int nt = 0; nt < 8; nt++) {
                uint32_t bb = bBase + nt * 8 * KT_ROWB + ko;
                uint32_t b0 = lds32(bb);
                uint32_t b1 = lds32(bb + 16);
                mma_f16(acc[nt][0], acc[nt][1], acc[nt][2], acc[nt][3],
                        a0, a1, a2, a3, b0, b1);
            }
        }
        __syncthreads();
    }

    float* dst = &g_ktv_part[(size_t)split * (HEADS * DH * DH) + (size_t)h * DH * DH];
    const int d2 = w * 16 + grow;
#pragma unroll
    for (int nt = 0; nt < 8; nt++) {
        const int d1 = nt * 8 + 2 * tg;
        *reinterpret_cast<float2*>(&dst[d2 * DH + d1]) = make_float2(acc[nt][0], acc[nt][1]);
        *reinterpret_cast<float2*>(&dst[(d2 + 8) * DH + d1]) = make_float2(acc[nt][2], acc[nt][3]);
    }
}

// ---------------------------------------------------------------------------
// out via mma.sync: 256 rows/block (grid 8x16, 256 thr) halves redundant
// M-partial traffic vs r14. A = Q fp16; B = M^T fp16 (summed from 8 fp32
// partials, fixed order). coarse fused (K fp32 path, exact).
// ---------------------------------------------------------------------------
#define OQ_ROWB 144                         // 64 halves + 16B pad
#define OSM_Q   0                           // 256*144 = 36864
#define OSM_MT  36864                       // 64*144  = 9216
#define OSM_QS  (OSM_MT + 9216)             // 46080
#define OSM_TOT (OSM_QS + 256)              // 46336

__global__ void __launch_bounds__(256) out_mma(float* __restrict__ coarse,
                                               float* __restrict__ out) {
    extern __shared__ char osm[];
    const uint32_t sb = smem_u32(osm);
    float* sQs = reinterpret_cast<float*>(osm + OSM_QS);

    const int h = blockIdx.x;
    const int nt = blockIdx.y;              // 0..15 (256 rows each)
    const int tid = threadIdx.x;
    const int lane = tid & 31;
    const int w = tid >> 5;                 // 0..7
    const int grow = lane >> 2;
    const int tg = lane & 3;

    // stage Q tile fp16: 256 rows x 128 B = 2048 chunks / 256 thr
    const __half* Qg = &g_qh[(size_t)h * HSTRIDE + (size_t)nt * 256 * DH];
#pragma unroll
    for (int i = 0; i < 8; i++) {
        int lin = tid + i * 256;
        int r = lin >> 3;
        int c = lin & 7;
        cp_async16(sb + OSM_Q + r * OQ_ROWB + c * 16, Qg + (size_t)r * DH + c * 8);
    }
    cp_commit();

    // stage M^T: sum 8 fp32 partials (fixed order), convert to fp16
    {
        const float* p0 = &g_ktv_part[(size_t)h * DH * DH];
#pragma unroll
        for (int i = 0; i < 8; i++) {
            int lin = tid + i * 256;        // 0..2047 float2 pairs
            int d2 = lin >> 5;
            int d1p = (lin & 31) * 2;
            float2 s = *reinterpret_cast<const float2*>(p0 + d2 * DH + d1p);
#pragma unroll
            for (int sp = 1; sp < KTV_SPLITS; sp++) {
                float2 v = *reinterpret_cast<const float2*>(
                    p0 + (size_t)sp * (HEADS * DH * DH) + d2 * DH + d1p);
                s.x += v.x; s.y += v.y;
            }
            *reinterpret_cast<__half2*>(osm + OSM_MT + d2 * OQ_ROWB + d1p * 2) =
                __floats2half2_rn(s.x, s.y);
        }
    }
    // qsum reduce (32 partials, fixed order)
    if (tid < 64) {
        float q = 0.f;
#pragma unroll
        for (int sp = 0; sp < 32; sp++) q += g_qsum_part[sp * (HEADS * DH) + h * 64 + tid];
        sQs[tid] = q;
    }
    cp_wait0();
    __syncthreads();

    // coarse: 1 row/thread via K fp32 (exact path)
    {
        const int n = nt * 256 + tid;
        const float* Kr = &g_kf[(size_t)h * HSTRIDE + (size_t)n * DH];
        float cacc = 0.f;
#pragma unroll
        for (int d4 = 0; d4 < 64; d4 += 4) {
            float4 k4 = *reinterpret_cast<const float4*>(&Kr[d4]);
            cacc += k4.x * sQs[d4] + k4.y * sQs[d4 + 1] + k4.z * sQs[d4 + 2] + k4.w * sQs[d4 + 3];
        }
        coarse[h * TOK + n] = cacc * SCALE;
    }

    // mma: warp w owns rows w*32..w*32+31 (2 m-tiles), all 64 cols (8 n-tiles)
    float acc[2][8][4];
#pragma unroll
    for (int mt = 0; mt < 2; mt++)
#pragma unroll
        for (int ct = 0; ct < 8; ct++)
#pragma unroll
            for (int c = 0; c < 4; c++) acc[mt][ct][c] = 0.f;

    const uint32_t aBase = sb + OSM_Q + (w * 32 + grow) * OQ_ROWB + tg * 4;
    const uint32_t bBase = sb + OSM_MT + grow * OQ_ROWB + tg * 4;

#pragma unroll
    for (int kk = 0; kk < 4; kk++) {
        const uint32_t ko = kk * 32;
        uint32_t a[2][4];
#pragma unroll
        for (int mt = 0; mt < 2; mt++) {
            uint32_t ab = aBase + mt * 16 * OQ_ROWB + ko;
            a[mt][0] = lds32(ab);
            a[mt][1] = lds32(ab + 8 * OQ_ROWB);
            a[mt][2] = lds32(ab + 16);
            a[mt][3] = lds32(ab + 8 * OQ_ROWB + 16);
        }
#pragma unroll
        for (int ct = 0; ct < 8; ct++) {
            uint32_t bb = bBase + ct * 8 * OQ_ROWB + ko;
            uint32_t b0 = lds32(bb);
            uint32_t b1 = lds32(bb + 16);
#pragma unroll
            for (int mt = 0; mt < 2; mt++)
                mma_f16(acc[mt][ct][0], acc[mt][ct][1], acc[mt][ct][2], acc[mt][ct][3],
                        a[mt][0], a[mt][1], a[mt][2], a[mt][3], b0, b1);
        }
    }

#pragma unroll
    for (int mt = 0; mt < 2; mt++) {
        const int n = nt * 256 + w * 32 + mt * 16 + grow;
        float* op = &out[((size_t)h * TOK + n) * DH];
#pragma unroll
        for (int ct = 0; ct < 8; ct++) {
            const int d = ct * 8 + 2 * tg;
            *reinterpret_cast<float2*>(&op[d]) =
                make_float2(acc[mt][ct][0] * SCALE, acc[mt][ct][1] * SCALE);
            *reinterpret_cast<float2*>(&op[8 * DH + d]) =
                make_float2(acc[mt][ct][2] * SCALE, acc[mt][ct][3] * SCALE);
        }
    }
}

// ---------------------------------------------------------------------------
extern "C" void kernel_launch(void* const* d_in, const int* in_sizes, int n_in,
                              void* d_out, int out_size) {
    const float* x = (const float*)d_in[0];   // [512, 4096]
    const float* W = (const float*)d_in[1];   // [512, 1536]
    const float* b = (const float*)d_in[2];   // [1536]

    float* coarse = (float*)d_out;
    float* out    = (float*)d_out + HEADS * TOK;

    __half *ahi, *bhi;
    cudaGetSymbolAddress((void**)&ahi, g_a_hi);
    cudaGetSymbolAddress((void**)&bhi, g_b_hi);

    cudaFuncSetAttribute(qkv_gemm_mma, cudaFuncAttributeMaxDynamicSharedMemorySize, SM_TOT);
    cudaFuncSetAttribute(ktv_mma, cudaFuncAttributeMaxDynamicSharedMemorySize, KTV_SMEM);
    cudaFuncSetAttribute(out_mma, cudaFuncAttributeMaxDynamicSharedMemorySize, OSM_TOT);

    conv_transpose2<<<dim3(XBLKS + QKVN / 32, EMB / 32), 256>>>(x, W, ahi, bhi);

    qkv_gemm_mma<<<dim3(QKVN / GBN, TOK / GBM), 256, SM_TOT>>>(b);

    ktv_mma<<<dim3(HEADS, KTV_SPLITS), 128, KTV_SMEM>>>();
    out_mma<<<dim3(HEADS, 16), 256, OSM_TOT>>>(coarse, out);
}

// round 17
// speedup vs baseline: 1.1903x; 1.0332x over previous
#include <cuda_runtime.h>
#include <cuda_fp16.h>
#include <cstdint>

#define TOK   4096
#define EMB   512
#define QKVN  1536
#define HEADS 8
#define DH    64
#define SCALE 0.125f

#define HSTRIDE (TOK * DH)           // 262144

#define KTV_SPLITS 8

// ---------------- scratch (device globals) ----------------
__device__ float g_kf[HEADS * TOK * DH];             // K fp32 [h][n][d] (coarse)
__device__ float g_qsum_part[32 * HEADS * DH];       // [m_block][h*64+d]
__device__ float g_ktv_part[KTV_SPLITS * HEADS * DH * DH];  // M^T partials [d2][d1]

__device__ __half g_a_hi[TOK * EMB];                 // A = x^T  [4096, 512]
__device__ __half g_b_hi[QKVN * EMB];                // B = W^T  [1536, 512]
__device__ __half g_qh[HEADS * TOK * DH];            // Q fp16 [h][n][d]
__device__ __half g_kT[HEADS * DH * TOK];            // K^T fp16 [h][d][n]
__device__ __half g_vT[HEADS * DH * TOK];            // V^T fp16 [h][d][n]

// ---------------- helpers ----------------
__device__ __forceinline__ uint32_t smem_u32(const void* p) {
    uint32_t a;
    asm("{ .reg .u64 t; cvta.to.shared.u64 t, %1; cvt.u32.u64 %0, t; }" : "=r"(a) : "l"(p));
    return a;
}
__device__ __forceinline__ uint32_t lds32(uint32_t a) {
    uint32_t v;
    asm volatile("ld.shared.b32 %0, [%1];" : "=r"(v) : "r"(a));
    return v;
}
__device__ __forceinline__ void sts_h(uint32_t a, float f) {
    unsigned short u = __half_as_ushort(__float2half_rn(f));
    asm volatile("st.shared.u16 [%0], %1;" :: "r"(a), "h"(u));
}
__device__ __forceinline__ void cp_async16(uint32_t saddr, const void* gaddr) {
    asm volatile("cp.async.cg.shared.global [%0], [%1], 16;" :: "r"(saddr), "l"(gaddr));
}
__device__ __forceinline__ void cp_commit() { asm volatile("cp.async.commit_group;"); }
__device__ __forceinline__ void cp_wait1()  { asm volatile("cp.async.wait_group 1;"); }
__device__ __forceinline__ void cp_wait0()  { asm volatile("cp.async.wait_group 0;"); }

__device__ __forceinline__ void mma_f16(float& c0, float& c1, float& c2, float& c3,
                                        uint32_t a0, uint32_t a1, uint32_t a2, uint32_t a3,
                                        uint32_t b0, uint32_t b1) {
    asm volatile(
        "mma.sync.aligned.m16n8k16.row.col.f32.f16.f16.f32 "
        "{%0,%1,%2,%3}, {%4,%5,%6,%7}, {%8,%9}, {%0,%1,%2,%3};"
        : "+f"(c0), "+f"(c1), "+f"(c2), "+f"(c3)
        : "r"(a0), "r"(a1), "r"(a2), "r"(a3), "r"(b0), "r"(b1));
}

// ---------------------------------------------------------------------------
// Merged pre-pass: transpose x->ahi and W->bhi, half2 stores
// ---------------------------------------------------------------------------
#define XBLKS (TOK / 32)      // 128
__global__ __launch_bounds__(256) void conv_transpose2(const float* __restrict__ x,
                                                       const float* __restrict__ W,
                                                       __half* __restrict__ ahi,
                                                       __half* __restrict__ bhi) {
    __shared__ float tile[32][33];
    int tid = threadIdx.x;
    int tx = tid & 31, ty = tid >> 5;
    int bx = blockIdx.x;
    const float* src;
    __half* dst;
    int Mcols, m0;
    if (bx < XBLKS) { src = x; dst = ahi; Mcols = TOK;  m0 = bx * 32; }
    else            { src = W; dst = bhi; Mcols = QKVN; m0 = (bx - XBLKS) * 32; }
    int k0 = blockIdx.y * 32;
#pragma unroll
    for (int j = 0; j < 4; j++)
        tile[ty + j * 8][tx] = src[(size_t)(k0 + ty + j * 8) * Mcols + m0 + tx];
    __syncthreads();
    int r2 = tid >> 4;
    int c2 = tid & 15;
#pragma unroll
    for (int j = 0; j < 2; j++) {
        int row = r2 + j * 16;
        int m = m0 + row;
        __half2 v = __floats2half2_rn(tile[c2 * 2][row], tile[c2 * 2 + 1][row]);
        *reinterpret_cast<__half2*>(&dst[(size_t)m * EMB + k0 + c2 * 2]) = v;
    }
}

// ---------------------------------------------------------------------------
// mma.sync QKV GEMM; epilogue: Q fp16 direct; K/V transposed via smem staging
// (coalesced 16B gmem stores instead of scattered 2B stores).
// ---------------------------------------------------------------------------
#define GBM 128
#define GBN 128
#define GBK 32
#define ROWB   80
#define TILE_B (128 * ROWB)
#define T_AHI  0
#define T_BHI  (1 * TILE_B)
#define STG_B  (2 * TILE_B)
#define SM_BIAS (2 * STG_B)          // 40960
#define SM_QS   (SM_BIAS + 512)
#define SM_TOT  (SM_QS + 1024)
#define TR_ROWB 272                  // transpose tile row stride (16B-aligned, +4 bank skew)

__global__ void __launch_bounds__(256, 2) qkv_gemm_mma(const float* __restrict__ bias) {
    extern __shared__ char smem[];
    const uint32_t sb = smem_u32(smem);
    const int tid  = threadIdx.x;
    const int wid  = tid >> 5;
    const int lane = tid & 31;
    const int g    = lane >> 2;
    const int tg   = lane & 3;
    const int wm   = wid >> 2;
    const int wn   = wid & 3;
    const int o0   = blockIdx.x * GBN;
    const int m0   = blockIdx.y * GBM;

    if (tid < 128) *reinterpret_cast<float*>(smem + SM_BIAS + tid * 4) = bias[o0 + tid];

    const __half* srcs[2] = {
        &g_a_hi[(size_t)m0 * EMB], &g_b_hi[(size_t)o0 * EMB]};

    auto issue = [&](int chunk) {
        const int kt = chunk * GBK;
        const uint32_t stage = sb + (chunk & 1) * STG_B;
#pragma unroll
        for (int t = 0; t < 2; t++) {
            const __half* gp = srcs[t] + kt;
            const uint32_t tb = stage + t * TILE_B;
#pragma unroll
            for (int i = 0; i < 2; i++) {
                int lin = tid + i * 256;
                int row = lin >> 2;
                int seg = lin & 3;
                cp_async16(tb + row * ROWB + seg * 16, gp + (size_t)row * EMB + seg * 8);
            }
        }
        cp_commit();
    };

    float acc[4][4][4];
#pragma unroll
    for (int i = 0; i < 4; i++)
#pragma unroll
        for (int j = 0; j < 4; j++)
#pragma unroll
            for (int c = 0; c < 4; c++) acc[i][j][c] = 0.f;

    issue(0);

    const uint32_t aRow0 = wm * 64 + g;
    const uint32_t bRow0 = wn * 32 + g;

    for (int chunk = 0; chunk < EMB / GBK; ++chunk) {
        if (chunk + 1 < EMB / GBK) { issue(chunk + 1); cp_wait1(); }
        else                       { cp_wait0(); }
        __syncthreads();

        const uint32_t stage = sb + (chunk & 1) * STG_B;

#pragma unroll
        for (int kk = 0; kk < 2; kk++) {
            const uint32_t klo = kk * 32 + tg * 4;

            uint32_t afr[4][4], bfr[4][2];
#pragma unroll
            for (int nt = 0; nt < 4; nt++) {
                uint32_t base = stage + (bRow0 + nt * 8) * ROWB + klo + T_BHI;
                bfr[nt][0] = lds32(base);
                bfr[nt][1] = lds32(base + 16);
            }
#pragma unroll
            for (int mt = 0; mt < 4; mt++) {
                uint32_t base = stage + (aRow0 + mt * 16) * ROWB + klo + T_AHI;
                afr[mt][0] = lds32(base);
                afr[mt][1] = lds32(base + 8 * ROWB);
                afr[mt][2] = lds32(base + 16);
                afr[mt][3] = lds32(base + 8 * ROWB + 16);
            }
#pragma unroll
            for (int mt = 0; mt < 4; mt++)
#pragma unroll
                for (int nt = 0; nt < 4; nt++)
                    mma_f16(acc[mt][nt][0], acc[mt][nt][1], acc[mt][nt][2], acc[mt][nt][3],
                            afr[mt][0], afr[mt][1], afr[mt][2], afr[mt][3],
                            bfr[nt][0], bfr[nt][1]);
        }
        __syncthreads();
    }

    const float* sbias = reinterpret_cast<const float*>(smem + SM_BIAS);

    if (o0 < 512) {
        // --- Q path: fp16 row-major direct + fused qsum partial ---
        const int h = o0 >> 6;
#pragma unroll
        for (int mt = 0; mt < 4; mt++) {
            const int m = m0 + wm * 64 + mt * 16 + g;
#pragma unroll
            for (int nt = 0; nt < 4; nt++) {
                const int off = wn * 32 + nt * 8 + 2 * tg;
                const int o = o0 + off;
                const int hh = (o >> 6) & 7;
                const int d = o & 63;
                const float bv0 = sbias[off], bv1 = sbias[off + 1];
                __half* dq = &g_qh[(size_t)hh * HSTRIDE];
                *reinterpret_cast<__half2*>(&dq[(size_t)m * DH + d]) =
                    __floats2half2_rn(acc[mt][nt][0] + bv0, acc[mt][nt][1] + bv1);
                *reinterpret_cast<__half2*>(&dq[(size_t)(m + 8) * DH + d]) =
                    __floats2half2_rn(acc[mt][nt][2] + bv0, acc[mt][nt][3] + bv1);
            }
        }
        (void)h;
        float* qs = reinterpret_cast<float*>(smem + SM_QS);
        float cs[8];
#pragma unroll
        for (int nt = 0; nt < 4; nt++)
#pragma unroll
            for (int j = 0; j < 2; j++) {
                const int off = wn * 32 + nt * 8 + 2 * tg + j;
                float s = 8.f * sbias[off];
#pragma unroll
                for (int mt = 0; mt < 4; mt++)
                    s += acc[mt][nt][j] + acc[mt][nt][j + 2];
                cs[nt * 2 + j] = s;
            }
#pragma unroll
        for (int i = 0; i < 8; i++) {
#pragma unroll
            for (int off = 4; off < 32; off <<= 1)
                cs[i] += __shfl_xor_sync(0xffffffffu, cs[i], off);
        }
        if (g == 0) {
#pragma unroll
            for (int nt = 0; nt < 4; nt++)
#pragma unroll
                for (int j = 0; j < 2; j++)
                    qs[wm * 128 + wn * 32 + nt * 8 + 2 * tg + j] = cs[nt * 2 + j];
        }
        __syncthreads();
        if (tid < 128)
            g_qsum_part[blockIdx.y * 512 + o0 + tid] = qs[tid] + qs[128 + tid];
    } else {
        // --- K/V path: stage transposed tile in smem, then coalesced stores ---
        const int part = o0 >> 9;   // 1 = K, 2 = V (uniform per block)
#pragma unroll
        for (int mt = 0; mt < 4; mt++) {
            const int mloc = wm * 64 + mt * 16 + g;
            const int m = m0 + mloc;
#pragma unroll
            for (int nt = 0; nt < 4; nt++) {
                const int off = wn * 32 + nt * 8 + 2 * tg;
                const float bv0 = sbias[off], bv1 = sbias[off + 1];
                const float v00 = acc[mt][nt][0] + bv0;
                const float v01 = acc[mt][nt][1] + bv1;
                const float v10 = acc[mt][nt][2] + bv0;
                const float v11 = acc[mt][nt][3] + bv1;
                if (part == 1) {
                    const int hh = (o0 + off) >> 6 & 7;
                    const int d = (o0 + off) & 63;
                    float* base = &g_kf[(size_t)hh * HSTRIDE];
                    *reinterpret_cast<float2*>(&base[(size_t)m * DH + d]) = make_float2(v00, v01);
                    *reinterpret_cast<float2*>(&base[(size_t)(m + 8) * DH + d]) = make_float2(v10, v11);
                }
                // transpose stage: T[off][mloc]
                const uint32_t t0 = sb + (uint32_t)off * TR_ROWB + mloc * 2;
                sts_h(t0, v00);
                sts_h(t0 + TR_ROWB, v01);
                sts_h(t0 + 16, v10);
                sts_h(t0 + TR_ROWB + 16, v11);
            }
        }
        __syncthreads();
        // coalesced write-out: 128 rows x 256 B = 2048 16B chunks / 256 thr
        __half* gT = (part == 1) ? g_kT : g_vT;
#pragma unroll
        for (int i = 0; i < 8; i++) {
            int lin = tid + i * 256;
            int row = lin >> 4;             // 0..127 (off)
            int ch  = lin & 15;             // 0..15
            const int o = o0 + row;
            const int hh = (o >> 6) & 7;
            const int dd = o & 63;
            float4 v = *reinterpret_cast<const float4*>(smem + row * TR_ROWB + ch * 16);
            *reinterpret_cast<float4*>(
                &gT[(size_t)hh * DH * TOK + (size_t)dd * TOK + m0 + ch * 8]) = v;
        }
    }
}

// ---------------------------------------------------------------------------
// KtV via mma.sync (A=V^T, B=K^T -> partials hold M^T[d2][d1]) — unchanged
// ---------------------------------------------------------------------------
#define KT_ROWB 528
#define KT_TILE (64 * KT_ROWB)
#define KTV_SMEM (2 * KT_TILE)

__global__ void __launch_bounds__(128) ktv_mma() {
    extern __shared__ char ksm[];
    const uint32_t sb = smem_u32(ksm);
    const int h = blockIdx.x;
    const int split = blockIdx.y;          // 0..7
    const int tid = threadIdx.x;
    const int lane = tid & 31;
    const int w = tid >> 5;
    const int grow = lane >> 2;
    const int tg = lane & 3;

    float acc[8][4];
#pragma unroll
    for (int nt = 0; nt < 8; nt++)
#pragma unroll
        for (int c = 0; c < 4; c++) acc[nt][c] = 0.f;

    const uint32_t aBase = sb + (w * 16 + grow) * KT_ROWB + tg * 4;
    const uint32_t bBase = sb + KT_TILE + grow * KT_ROWB + tg * 4;

    for (int cc = 0; cc < 2; cc++) {
        const __half* Asrc = &g_vT[(size_t)h * DH * TOK + split * 512 + cc * 256];
        const __half* Bsrc = &g_kT[(size_t)h * DH * TOK + split * 512 + cc * 256];
#pragma unroll
        for (int i = 0; i < 16; i++) {
            int lin = tid + i * 128;
            int r = lin >> 5;
            int c = lin & 31;
            cp_async16(sb + r * KT_ROWB + c * 16, Asrc + (size_t)r * TOK + c * 8);
            cp_async16(sb + KT_TILE + r * KT_ROWB + c * 16, Bsrc + (size_t)r * TOK + c * 8);
        }
        cp_commit();
        cp_wait0();
        __syncthreads();

#pragma unroll
        for (int kk = 0; kk < 16; kk++) {
            const uint32_t ko = kk * 32;
            uint32_t a0 = lds32(aBase + ko);
            uint32_t a1 = lds32(aBase + 8 * KT_ROWB + ko);
            uint32_t a2 = lds32(aBase + ko + 16);
            uint32_t a3 = lds32(aBase + 8 * KT_ROWB + ko + 16);
#pragma unroll
            for (int nt = 0; nt < 8; nt++) {
                uint32_t bb = bBase + nt * 8 * KT_ROWB + ko;
                uint32_t b0 = lds32(bb);
                uint32_t b1 = lds32(bb + 16);
                mma_f16(acc[nt][0], acc[nt][1], acc[nt][2], acc[nt][3],
                        a0, a1, a2, a3, b0, b1);
            }
        }
        __syncthreads();
    }

    float* dst = &g_ktv_part[(size_t)split * (HEADS * DH * DH) + (size_t)h * DH * DH];
    const int d2 = w * 16 + grow;
#pragma unroll
    for (int nt = 0; nt < 8; nt++) {
        const int d1 = nt * 8 + 2 * tg;
        *reinterpret_cast<float2*>(&dst[d2 * DH + d1]) = make_float2(acc[nt][0], acc[nt][1]);
        *reinterpret_cast<float2*>(&dst[(d2 + 8) * DH + d1]) = make_float2(acc[nt][2], acc[nt][3]);
    }
}

// ---------------------------------------------------------------------------
// out via mma.sync: 256 rows/block (grid 8x16, 256 thr) — unchanged from r16
// ---------------------------------------------------------------------------
#define OQ_ROWB 144
#define OSM_Q   0                           // 256*144 = 36864
#define OSM_MT  36864                       // 64*144  = 9216
#define OSM_QS  (OSM_MT + 9216)             // 46080
#define OSM_TOT (OSM_QS + 256)              // 46336

__global__ void __launch_bounds__(256) out_mma(float* __restrict__ coarse,
                                               float* __restrict__ out) {
    extern __shared__ char osm[];
    const uint32_t sb = smem_u32(osm);
    float* sQs = reinterpret_cast<float*>(osm + OSM_QS);

    const int h = blockIdx.x;
    const int nt = blockIdx.y;              // 0..15
    const int tid = threadIdx.x;
    const int lane = tid & 31;
    const int w = tid >> 5;                 // 0..7
    const int grow = lane >> 2;
    const int tg = lane & 3;

    const __half* Qg = &g_qh[(size_t)h * HSTRIDE + (size_t)nt * 256 * DH];
#pragma unroll
    for (int i = 0; i < 8; i++) {
        int lin = tid + i * 256;
        int r = lin >> 3;
        int c = lin & 7;
        cp_async16(sb + OSM_Q + r * OQ_ROWB + c * 16, Qg + (size_t)r * DH + c * 8);
    }
    cp_commit();

    {
        const float* p0 = &g_ktv_part[(size_t)h * DH * DH];
#pragma unroll
        for (int i = 0; i < 8; i++) {
            int lin = tid + i * 256;
            int d2 = lin >> 5;
            int d1p = (lin & 31) * 2;
            float2 s = *reinterpret_cast<const float2*>(p0 + d2 * DH + d1p);
#pragma unroll
            for (int sp = 1; sp < KTV_SPLITS; sp++) {
                float2 v = *reinterpret_cast<const float2*>(
                    p0 + (size_t)sp * (HEADS * DH * DH) + d2 * DH + d1p);
                s.x += v.x; s.y += v.y;
            }
            *reinterpret_cast<__half2*>(osm + OSM_MT + d2 * OQ_ROWB + d1p * 2) =
                __floats2half2_rn(s.x, s.y);
        }
    }
    if (tid < 64) {
        float q = 0.f;
#pragma unroll
        for (int sp = 0; sp < 32; sp++) q += g_qsum_part[sp * (HEADS * DH) + h * 64 + tid];
        sQs[tid] = q;
    }
    cp_wait0();
    __syncthreads();

    {
        const int n = nt * 256 + tid;
        const float* Kr = &g_kf[(size_t)h * HSTRIDE + (size_t)n * DH];
        float cacc = 0.f;
#pragma unroll
        for (int d4 = 0; d4 < 64; d4 += 4) {
            float4 k4 = *reinterpret_cast<const float4*>(&Kr[d4]);
            cacc += k4.x * sQs[d4] + k4.y * sQs[d4 + 1] + k4.z * sQs[d4 + 2] + k4.w * sQs[d4 + 3];
        }
        coarse[h * TOK + n] = cacc * SCALE;
    }

    float acc[2][8][4];
#pragma unroll
    for (int mt = 0; mt < 2; mt++)
#pragma unroll
        for (int ct = 0; ct < 8; ct++)
#pragma unroll
            for (int c = 0; c < 4; c++) acc[mt][ct][c] = 0.f;

    const uint32_t aBase = sb + OSM_Q + (w * 32 + grow) * OQ_ROWB + tg * 4;
    const uint32_t bBase = sb + OSM_MT + grow * OQ_ROWB + tg * 4;

#pragma unroll
    for (int kk = 0; kk < 4; kk++) {
        const uint32_t ko = kk * 32;
        uint32_t a[2][4];
#pragma unroll
        for (int mt = 0; mt < 2; mt++) {
            uint32_t ab = aBase + mt * 16 * OQ_ROWB + ko;
            a[mt][0] = lds32(ab);
            a[mt][1] = lds32(ab + 8 * OQ_ROWB);
            a[mt][2] = lds32(ab + 16);
            a[mt][3] = lds32(ab + 8 * OQ_ROWB + 16);
        }
#pragma unroll
        for (int ct = 0; ct < 8; ct++) {
            uint32_t bb = bBase + ct * 8 * OQ_ROWB + ko;
            uint32_t b0 = lds32(bb);
            uint32_t b1 = lds32(bb + 16);
#pragma unroll
            for (int mt = 0; mt < 2; mt++)
                mma_f16(acc[mt][ct][0], acc[mt][ct][1], acc[mt][ct][2], acc[mt][ct][3],
                        a[mt][0], a[mt][1], a[mt][2], a[mt][3], b0, b1);
        }
    }

#pragma unroll
    for (int mt = 0; mt < 2; mt++) {
        const int n = nt * 256 + w * 32 + mt * 16 + grow;
        float* op = &out[((size_t)h * TOK + n) * DH];
#pragma unroll
        for (int ct = 0; ct < 8; ct++) {
            const int d = ct * 8 + 2 * tg;
            *reinterpret_cast<float2*>(&op[d]) =
                make_float2(acc[mt][ct][0] * SCALE, acc[mt][ct][1] * SCALE);
            *reinterpret_cast<float2*>(&op[8 * DH + d]) =
                make_float2(acc[mt][ct][2] * SCALE, acc[mt][ct][3] * SCALE);
        }
    }
}

// ---------------------------------------------------------------------------
extern "C" void kernel_launch(void* const* d_in, const int* in_sizes, int n_in,
                              void* d_out, int out_size) {
    const float* x = (const float*)d_in[0];   // [512, 4096]
    const float* W = (const float*)d_in[1];   // [512, 1536]
    const float* b = (const float*)d_in[2];   // [1536]

    float* coarse = (float*)d_out;
    float* out    = (float*)d_out + HEADS * TOK;

    __half *ahi, *bhi;
    cudaGetSymbolAddress((void**)&ahi, g_a_hi);
    cudaGetSymbolAddress((void**)&bhi, g_b_hi);

    cudaFuncSetAttribute(qkv_gemm_mma, cudaFuncAttributeMaxDynamicSharedMemorySize, SM_TOT);
    cudaFuncSetAttribute(ktv_mma, cudaFuncAttributeMaxDynamicSharedMemorySize, KTV_SMEM);
    cudaFuncSetAttribute(out_mma, cudaFuncAttributeMaxDynamicSharedMemorySize, OSM_TOT);

    conv_transpose2<<<dim3(XBLKS + QKVN / 32, EMB / 32), 256>>>(x, W, ahi, bhi);

    qkv_gemm_mma<<<dim3(QKVN / GBN, TOK / GBM), 256, SM_TOT>>>(b);

    ktv_mma<<<dim3(HEADS, KTV_SPLITS), 128, KTV_SMEM>>>();
    out_mma<<<dim3(HEADS, 16), 256, OSM_TOT>>>(coarse, out);
}